// round 14
// baseline (speedup 1.0000x reference)
#include <cuda_runtime.h>
#include <cuda_fp16.h>
#include <cstdint>

// T=4, B=64, C=512, N=196, H=8, D=64
#define EPS_         1e-5f
#define MARGIN_QKV   2e-3f
#define MARGIN_PROJ  1.2e-3f

constexpr size_t BITS_SZ = 3ULL * 4 * 64 * 8 * 196;     // packed u64
constexpr size_t BR_BITS = 4ULL * 64 * 8 * 196;
constexpr size_t O_ELEMS = 4ULL * 64 * 512 * 196;
constexpr size_t XT_SZ   = 4ULL * 64 * 196 * 512;       // [t,b,n,c]
constexpr int CAP0 = 1 << 20;
constexpr int CAP1 = 1 << 18;
constexpr int CAPB = 32;                 // per-(b,n) fixup bucket capacity
constexpr int NBKT = 64 * 196;           // 12544
constexpr int STG    = 16384;            // stage: Wh@0 | Xh@8192, 64B pitch rows
constexpr int NSTAGE = 6;
constexpr int SMEMSZ = NSTAGE * STG;     // 98304 -> 2 CTAs/SM

// attn kernel smem layout (bytes)
constexpr int A_SQ  = 0;                 // u64[200]
constexpr int A_SK  = 1600;
constexpr int A_SV  = 3200;
constexpr int A_KC  = 4800;              // u64[64][4]
constexpr int A_VC  = 6848;
constexpr int A_QF  = 8960;              // fp16 [208][pitch 144B]
constexpr int A_CNT = 38912;             // fp16 [64][pitch 144B]
constexpr int A_O1  = 8960;              // f32 [196*64] (aliases QF/CNT after mma)
constexpr int A_SZ  = 59136;             // -> 2 CTAs/SM

__device__ __align__(16) unsigned long long g_bits[BITS_SZ];
__device__ __align__(16) float              g_xT[XT_SZ];     // fp32 (fixup only)
__device__ __align__(16) __half             g_xh[XT_SZ];
__device__ __align__(16) __half             g_s2h[XT_SZ];    // attn_lif spikes fp16
__device__ __align__(16) __half             g_wh[2048 * 512];
__device__ float    g_inv[2048];
__device__ float    g_shift[2048];
__device__ unsigned g_fix0[CAP0];        // overflow list (QKV)
__device__ unsigned g_fix1[CAP1];
__device__ unsigned g_fixb[NBKT * CAPB]; // bucketed QKV flags
__device__ int      g_fbcnt[NBKT];
__device__ int      g_cnt[2];

// ---------------------------------------------------------------------------
// Fused prep: [0,4096) w->fp16 | [4096,32768) x_split | [32768,..) bn+counters
// ---------------------------------------------------------------------------
__global__ void prep_all(const float* __restrict__ x,     const float* __restrict__ w,
                         const float* __restrict__ gamma, const float* __restrict__ beta,
                         const float* __restrict__ mean,  const float* __restrict__ var) {
    __shared__ float tile[32][33];
    const int bid = blockIdx.x, tid = threadIdx.x;
    if (bid < 4096) {                       // w fp32 -> fp16
        int i = bid * 256 + tid;
        g_wh[i] = __float2half(w[i]);
    } else if (bid < 32768) {               // x [t,b,c,n] -> xT f32 + xh fp16 [t,b,n,c]
        int id = bid - 4096;
        int c0 = (id & 15) * 32, n0 = ((id >> 4) % 7) * 32, tb = id / 112;
        int tx = tid & 31, ty = tid >> 5;
#pragma unroll
        for (int i = 0; i < 4; i++) {
            int c = ty + i * 8, n = tx;
            float v = (n0 + n < 196) ? x[((size_t)tb * 512 + c0 + c) * 196 + n0 + n] : 0.f;
            tile[c][n] = v;
        }
        __syncthreads();
#pragma unroll
        for (int i = 0; i < 4; i++) {
            int n = ty + i * 8, c = tx;
            if (n0 + n < 196) {
                size_t idx = ((size_t)tb * 196 + n0 + n) * 512 + c0 + c;
                float v = tile[c][n];
                g_xT[idx] = v;
                g_xh[idx] = __float2half(v);
            }
        }
    } else if (bid < 32776) {               // BN prep + counter zero
        int i = (bid - 32768) * 256 + tid;
        if (bid == 32768 && tid < 2) g_cnt[tid] = 0;
        if (i < 2048) {
            float inv = gamma[i] * rsqrtf(var[i] + EPS_);
            g_inv[i]   = inv;
            g_shift[i] = beta[i] - mean[i] * inv;
        }
    } else {                                // zero bucket counters
        int i = (bid - 32776) * 256 + tid;
        if (i < NBKT) g_fbcnt[i] = 0;
    }
}

// ---------------------------------------------------------------------------
__device__ __forceinline__ void ldsm4(uint32_t addr, uint32_t* d) {
    asm volatile("ldmatrix.sync.aligned.m8n8.x4.shared.b16 {%0,%1,%2,%3}, [%4];"
        : "=r"(d[0]), "=r"(d[1]), "=r"(d[2]), "=r"(d[3]) : "r"(addr));
}
__device__ __forceinline__ void mma_f16(float* c, const uint32_t* a, const uint32_t* b) {
    asm volatile(
        "mma.sync.aligned.m16n8k16.row.col.f32.f16.f16.f32 "
        "{%0,%1,%2,%3}, {%4,%5,%6,%7}, {%8,%9}, {%0,%1,%2,%3};"
        : "+f"(c[0]), "+f"(c[1]), "+f"(c[2]), "+f"(c[3])
        : "r"(a[0]), "r"(a[1]), "r"(a[2]), "r"(a[3]), "r"(b[0]), "r"(b[1]));
}
__device__ __forceinline__ void cpa16(uint32_t dst, const void* src) {
    asm volatile("cp.async.cg.shared.global [%0], [%1], 16;" :: "r"(dst), "l"(src));
}
// XOR-swizzled address: 64B rows, chunk q permuted by ((row>>1)&3).
__device__ __forceinline__ uint32_t sw_addr(uint32_t base, int row, int kElem) {
    int q = kElem >> 3;
    return base + row * 64 + (((q ^ ((row >> 1) & 3)) << 4));
}

// One stage load (256 thr): regions Wh@0, Xh@8192 (128 rows x 64B each).
template<int IS_PROJ>
__device__ __forceinline__ void stage_load(uint32_t sbase, int kc, int wrow0, int b, int n0) {
    const __half* __restrict__ xs = IS_PROJ ? g_s2h : g_xh;
#pragma unroll
    for (int p = 0; p < 2; p++) {
        int c = threadIdx.x * 2 + p;
        int row = c >> 2, q = c & 3;
        uint32_t doff = (uint32_t)(row * 64 + ((q ^ ((row >> 1) & 3)) << 4));
        cpa16(sbase + doff, g_wh + (size_t)(wrow0 + row) * 512 + kc + q * 8);
        int t = row >> 5, n = row & 31;
        cpa16(sbase + 8192 + doff,
              xs + ((size_t)((t * 64 + b) * 196 + n0 + n)) * 512 + kc + q * 8);
    }
    asm volatile("cp.async.commit_group;");
}

// ---------------------------------------------------------------------------
// SINGLE-PASS fp16 mma.sync GEMM + BN + LIF. 6-stage cp.async, 2 CTAs/SM.
// ---------------------------------------------------------------------------
template<int IS_PROJ>
__global__ __launch_bounds__(256, 2) void mma_gemm_lif(float* __restrict__ o_out) {
    extern __shared__ __align__(16) unsigned char SM[];
    const int n0   = min((int)blockIdx.x * 32, 164);   // overlap tile: all n valid
    const int o128 = blockIdx.y << 7;
    const int b    = blockIdx.z;
    const int wrow0 = (IS_PROJ ? 1536 : 0) + o128;
    const int tid = threadIdx.x, lane = tid & 31, warp = tid >> 5;
    const int wt = warp & 3, oh = warp >> 2;
    const float MARGIN = IS_PROJ ? MARGIN_PROJ : MARGIN_QKV;
    const uint32_t sb = (uint32_t)__cvta_generic_to_shared(SM);

    float acc[4][4][4];
#pragma unroll
    for (int a = 0; a < 4; a++)
#pragma unroll
        for (int c = 0; c < 4; c++)
#pragma unroll
            for (int d = 0; d < 4; d++) acc[a][c][d] = 0.f;

    const int aRow = lane & 15,                aK = (lane >> 4) << 3;
    const int bRow = (lane & 7) | ((lane >> 4) << 3), bK = ((lane >> 3) & 1) << 3;

#pragma unroll
    for (int s = 0; s < 5; s++)
        stage_load<IS_PROJ>(sb + s * STG, s * 32, wrow0, b, n0);

#pragma unroll 1
    for (int i = 0; i < 16; i++) {
        if (i <= 11)      asm volatile("cp.async.wait_group 4;");
        else if (i == 12) asm volatile("cp.async.wait_group 3;");
        else if (i == 13) asm volatile("cp.async.wait_group 2;");
        else if (i == 14) asm volatile("cp.async.wait_group 1;");
        else              asm volatile("cp.async.wait_group 0;");
        __syncthreads();
        if (i + 5 < 16)
            stage_load<IS_PROJ>(sb + ((i + 5) % 6) * STG, (i + 5) * 32, wrow0, b, n0);

        const uint32_t st  = sb + (i % 6) * STG;
        const uint32_t s_x = st + 8192;
#pragma unroll
        for (int kk = 0; kk < 32; kk += 16) {
            uint32_t A[4][4], B[4][2];
#pragma unroll
            for (int ot = 0; ot < 4; ot++)
                ldsm4(sw_addr(st, oh * 64 + ot * 16 + aRow, kk + aK), A[ot]);
#pragma unroll
            for (int n2 = 0; n2 < 2; n2++) {
                uint32_t d[4];
                ldsm4(sw_addr(s_x, wt * 32 + n2 * 16 + bRow, kk + bK), d);
                B[n2 * 2][0] = d[0]; B[n2 * 2][1] = d[1];
                B[n2 * 2 + 1][0] = d[2]; B[n2 * 2 + 1][1] = d[3];
            }
#pragma unroll
            for (int ot = 0; ot < 4; ot++)
#pragma unroll
                for (int nt = 0; nt < 4; nt++) mma_f16(acc[ot][nt], A[ot], B[nt]);
        }
    }

    // ---- epilogue: acc -> ys[4t][128o][33] (smem), then BN + LIF
    __syncthreads();
    float* ys = (float*)SM;
    {
        const int cg = lane >> 2, ctg = lane & 3;
#pragma unroll
        for (int ot = 0; ot < 4; ot++)
#pragma unroll
            for (int nt = 0; nt < 4; nt++) {
                int row = oh * 64 + ot * 16 + cg, col = nt * 8 + ctg * 2;
                ys[(wt * 128 + row) * 33 + col]         = acc[ot][nt][0];
                ys[(wt * 128 + row) * 33 + col + 1]     = acc[ot][nt][1];
                ys[(wt * 128 + row + 8) * 33 + col]     = acc[ot][nt][2];
                ys[(wt * 128 + row + 8) * 33 + col + 1] = acc[ot][nt][3];
            }
    }
    __syncthreads();

    if (!IS_PROJ) {
        const int oq2 = warp & 3, ng = warp >> 2;
        const int o_loc = oq2 * 32 + lane;
        const int og = o128 + o_loc;
        const int br = og >> 9, o_in = og & 511;
        const float inv = g_inv[br * 512 + o_in], shf = g_shift[br * 512 + o_in];
        const int h = (o_in >> 6) & 7, half = (o_loc >> 5) & 1;
#pragma unroll
        for (int j = 0; j < 16; j++) {
            const int nl = ng * 16 + j, n = n0 + nl;
            float v = 0.f;
            bool bad = false, sp[4];
#pragma unroll
            for (int t = 0; t < 4; t++) {
                float y = fmaf(ys[(t * 128 + o_loc) * 33 + nl], inv, shf);
                v += (y - v) * 0.5f;
                float d = v - 1.0f;
                if (fabsf(d) < MARGIN) bad = true;
                sp[t] = d >= 0.f;
                if (sp[t]) v = 0.f;
            }
#pragma unroll
            for (int t = 0; t < 4; t++) {
                uint32_t m = __ballot_sync(0xffffffffu, sp[t]);
                if (lane == 0)
                    ((uint32_t*)g_bits)[((((size_t)br * 4 + t) * 64 + b) * 8 + h) * 392
                                        + n * 2 + half] = m;
            }
            if (bad) {
                int bkt = b * 196 + n;
                int s = atomicAdd(&g_fbcnt[bkt], 1);
                if (s < CAPB) {
                    g_fixb[bkt * CAPB + s] = ((unsigned)br << 9) | o_in;
                } else {
                    int s2 = atomicAdd(&g_cnt[0], 1);
                    if (s2 < CAP0)
                        g_fix0[s2] = ((unsigned)br << 23) | ((unsigned)b << 17) |
                                     ((unsigned)o_in << 8) | n;
                }
            }
        }
    } else {
        const int n = n0 + lane;
#pragma unroll
        for (int j = 0; j < 16; j++) {
            const int o_in = o128 + warp * 16 + j;
            const float inv = g_inv[1536 + o_in], shf = g_shift[1536 + o_in];
            float v = 0.f;
            bool bad = false;
#pragma unroll
            for (int t = 0; t < 4; t++) {
                float y = fmaf(ys[(t * 128 + warp * 16 + j) * 33 + lane], inv, shf);
                v += (y - v) * 0.5f;
                float d = v - 1.0f;
                if (fabsf(d) < MARGIN) bad = true;
                bool s = d >= 0.f;
                o_out[((size_t)(t * 64 + b) * 512 + o_in) * 196 + n] = s ? 1.f : 0.f;
                if (s) v = 0.f;
            }
            if (bad) {
                int s = atomicAdd(&g_cnt[1], 1);
                if (s < CAP1)
                    g_fix1[s] = ((unsigned)b << 17) | ((unsigned)o_in << 8) | n;
            }
        }
    }
}

// ---------------------------------------------------------------------------
// QKV fixup: bucketed by (b,n). One CTA per bucket stages the 4 X rows in
// smem once; each entry streams only its W row. STRICT sequential c order
// (bit-identical to the reference-matching recompute). Blocks >= NBKT handle
// the overflow list (rare) with global X reads, same order.
// ---------------------------------------------------------------------------
__global__ void fixup_qkv(const float* __restrict__ w) {
    __shared__ float xs[4][512];
    const int bkt = blockIdx.x;
    if (bkt < NBKT) {
        int cnt = g_fbcnt[bkt];
        if (cnt == 0) return;
        if (cnt > CAPB) cnt = CAPB;
        const int b = bkt / 196, n = bkt % 196;
        for (int i = threadIdx.x; i < 2048; i += 128) {
            int t = i >> 9, c = i & 511;
            xs[t][c] = g_xT[((size_t)((t * 64 + b) * 196 + n)) * 512 + c];
        }
        __syncthreads();
        for (int e = threadIdx.x; e < cnt; e += 128) {
            unsigned u = g_fixb[bkt * CAPB + e];
            int o = u & 511, br = u >> 9;
            const float* wr = w + ((size_t)br * 512 + o) * 512;
            float inv = g_inv[br * 512 + o], shf = g_shift[br * 512 + o];
            float v = 0.f;
#pragma unroll 1
            for (int t = 0; t < 4; t++) {
                float s = 0.f;
#pragma unroll 4
                for (int c = 0; c < 512; c += 4) {
                    float4 a = *(const float4*)(wr + c);
                    s = fmaf(a.x, xs[t][c],     s);
                    s = fmaf(a.y, xs[t][c + 1], s);
                    s = fmaf(a.z, xs[t][c + 2], s);
                    s = fmaf(a.w, xs[t][c + 3], s);
                }
                float y = fmaf(s, inv, shf);
                v += (y - v) * 0.5f;
                bool sp = (v - 1.0f) >= 0.f;
                int h = o >> 6, d = o & 63;
                uint32_t* wp = ((uint32_t*)g_bits) +
                    ((((size_t)br * 4 + t) * 64 + b) * 8 + h) * 392 + n * 2 + (d >> 5);
                uint32_t m = 1u << (d & 31);
                if (sp) atomicOr(wp, m); else atomicAnd(wp, ~m);
                if (sp) v = 0.f;
            }
        }
    } else {
        // overflow list
        int cnt = g_cnt[0];
        if (cnt > CAP0) cnt = CAP0;
        int base = (bkt - NBKT) * 128 + threadIdx.x;
        for (int e = base; e < cnt; e += 64 * 128) {
            unsigned u = g_fix0[e];
            int n = u & 255, o = (u >> 8) & 511, bb = (u >> 17) & 63;
            int br = (int)(u >> 23);
            const float* wr = w + ((size_t)br * 512 + o) * 512;
            float inv = g_inv[br * 512 + o], shf = g_shift[br * 512 + o];
            float v = 0.f;
#pragma unroll 1
            for (int t = 0; t < 4; t++) {
                const float* xr = g_xT + ((size_t)((t * 64 + bb) * 196 + n)) * 512;
                float s = 0.f;
#pragma unroll 4
                for (int c = 0; c < 512; c += 4) {
                    float4 a  = *(const float4*)(wr + c);
                    float4 xv = *(const float4*)(xr + c);
                    s = fmaf(a.x, xv.x, s);
                    s = fmaf(a.y, xv.y, s);
                    s = fmaf(a.z, xv.z, s);
                    s = fmaf(a.w, xv.w, s);
                }
                float y = fmaf(s, inv, shf);
                v += (y - v) * 0.5f;
                bool sp = (v - 1.0f) >= 0.f;
                int h = o >> 6, d = o & 63;
                uint32_t* wp = ((uint32_t*)g_bits) +
                    ((((size_t)br * 4 + t) * 64 + bb) * 8 + h) * 392 + n * 2 + (d >> 5);
                uint32_t m = 1u << (d & 31);
                if (sp) atomicOr(wp, m); else atomicAnd(wp, ~m);
                if (sp) v = 0.f;
            }
        }
    }
}

// ---------------------------------------------------------------------------
// Proj fixup (list style, small count). Sequential order, patches o_out.
// ---------------------------------------------------------------------------
__global__ void fixup_proj(const float* __restrict__ w, float* __restrict__ o_out) {
    int cnt = g_cnt[1];
    if (cnt > CAP1) cnt = CAP1;
    for (int e = blockIdx.x * blockDim.x + threadIdx.x; e < cnt;
         e += gridDim.x * blockDim.x) {
        unsigned u = g_fix1[e];
        int n = u & 255, o = (u >> 8) & 511, bb = (u >> 17) & 63;
        const float* wr = w + ((size_t)3 * 512 + o) * 512;
        float inv = g_inv[1536 + o], shf = g_shift[1536 + o];
        float v = 0.f;
#pragma unroll 1
        for (int t = 0; t < 4; t++) {
            const __half* xr = g_s2h + ((size_t)((t * 64 + bb) * 196 + n)) * 512;
            float s = 0.f;
#pragma unroll 4
            for (int c = 0; c < 512; c += 2) {
                __half2 p = *(const __half2*)(xr + c);
                s = fmaf(wr[c],     __low2float(p),  s);
                s = fmaf(wr[c + 1], __high2float(p), s);
            }
            float y = fmaf(s, inv, shf);
            v += (y - v) * 0.5f;
            bool sp = (v - 1.0f) >= 0.f;
            o_out[((size_t)(t * 64 + bb) * 512 + o) * 196 + n] = sp ? 1.f : 0.f;
            if (sp) v = 0.f;
        }
    }
}

// ---------------------------------------------------------------------------
// Attention per (b,h), all 4 t in-block. LIF state in registers; sk words
// hoisted per lane; float4 attn stores; AV via exact fp16 MMA.
// ---------------------------------------------------------------------------
__global__ __launch_bounds__(512, 2) void attn_kernel(float* __restrict__ attn_out) {
    extern __shared__ __align__(16) unsigned char AS[];
    const int bh = blockIdx.x;
    const int b = bh >> 3, h = bh & 7;

    unsigned long long* sq = (unsigned long long*)(AS + A_SQ);
    unsigned long long* sk = (unsigned long long*)(AS + A_SK);
    unsigned long long* sv = (unsigned long long*)(AS + A_SV);
    unsigned long long* kc = (unsigned long long*)(AS + A_KC);
    unsigned long long* vc = (unsigned long long*)(AS + A_VC);
    float* o1b = (float*)(AS + A_O1);
    const uint32_t sb = (uint32_t)__cvta_generic_to_shared(AS);

    const int tid = threadIdx.x;
    const int d = tid & 63, g = tid >> 6;
    const int warp = tid >> 5, lane = tid & 31;
    const int aRow = lane & 15, aK = (lane >> 4) << 3;
    const int bRow = (lane & 7) | ((lane >> 4) << 3), bK2 = ((lane >> 3) & 1) << 3;

    float vst[25];
#pragma unroll
    for (int j = 0; j < 25; j++) vst[j] = 0.f;

#pragma unroll 1
    for (int t = 0; t < 4; t++) {
        __syncthreads();
        size_t qidx = ((size_t)(t * 64 + b) * 8 + h) * 196;
        for (int i = tid; i < 600; i += 512) {
            if (i < 196)      sq[i]       = g_bits[qidx + i];
            else if (i < 392) sk[i - 196] = g_bits[BR_BITS + qidx + (i - 196)];
            else if (i < 588) sv[i - 392] = g_bits[2 * BR_BITS + qidx + (i - 392)];
            else {
                int j = i - 588;
                if (j < 4)      sq[196 + j] = 0ull;
                else if (j < 8) sk[192 + j] = 0ull;
                else            sv[188 + j] = 0ull;
            }
        }
        __syncthreads();
        // kcol/vcol + qf build (fp16 0/1 from bits)
        {
            int e = tid & 63, wd = (tid >> 6) & 3, sel = tid >> 8;
            const unsigned long long* src = sel ? sv : sk;
            int m0 = wd * 64;
            int m1 = m0 + 64 < 196 ? m0 + 64 : 196;
            unsigned long long a = 0ull;
            for (int m = m0; m < m1; m++)
                a |= ((src[m] >> e) & 1ull) << (m - m0);
            if (sel) vc[e * 4 + wd] = a; else kc[e * 4 + wd] = a;
        }
        for (int i = tid; i < 208 * 32; i += 512) {
            int n = i >> 5, ep = (i & 31) << 1;
            unsigned long long bits = (n < 196) ? sq[n] : 0ull;
            __half2 hv = __floats2half2_rn((float)((bits >> ep) & 1ull),
                                           (float)((bits >> (ep + 1)) & 1ull));
            *(__half2*)(AS + A_QF + n * 144 + ep * 2) = hv;
        }
        __syncthreads();
        // attn output: sk hoisted to regs, float4 stores (rows are 16B-aligned)
        {
            size_t abase = ((size_t)(t * 64 + b) * 8 + h) * 38416;
            unsigned long long k0[4], k1[4];
#pragma unroll
            for (int j = 0; j < 4; j++) k0[j] = sk[lane * 4 + j];
            if (lane < 17) {
#pragma unroll
                for (int j = 0; j < 4; j++) k1[j] = sk[128 + lane * 4 + j];
            }
#pragma unroll 1
            for (int r = 0; r < 13; r++) {
                int n = warp + (r << 4);
                if (n < 196) {
                    unsigned long long qn = sq[n];
                    float4* out = (float4*)(attn_out + abase + (size_t)n * 196);
                    out[lane] = make_float4(
                        (float)__popcll(qn & k0[0]) * 0.125f,
                        (float)__popcll(qn & k0[1]) * 0.125f,
                        (float)__popcll(qn & k0[2]) * 0.125f,
                        (float)__popcll(qn & k0[3]) * 0.125f);
                    if (lane < 17)
                        out[32 + lane] = make_float4(
                            (float)__popcll(qn & k1[0]) * 0.125f,
                            (float)__popcll(qn & k1[1]) * 0.125f,
                            (float)__popcll(qn & k1[2]) * 0.125f,
                            (float)__popcll(qn & k1[3]) * 0.125f);
                }
            }
        }
        // cnt_d build (fp16, c<=196 exact)
        for (int i = tid; i < 4096; i += 512) {
            int dd = i >> 6, e = i & 63;
            int c = __popcll(kc[e * 4] & vc[dd * 4]) + __popcll(kc[e * 4 + 1] & vc[dd * 4 + 1])
                  + __popcll(kc[e * 4 + 2] & vc[dd * 4 + 2]) + __popcll(kc[e * 4 + 3] & vc[dd * 4 + 3]);
            *(__half*)(AS + A_CNT + dd * 144 + e * 2) = __int2half_rn(c);
        }
        __syncthreads();
        // o1 = qf @ cnt_d (exact integer math via fp16 MMA)
        float acc[8][4];
#pragma unroll
        for (int nt = 0; nt < 8; nt++)
#pragma unroll
            for (int q4 = 0; q4 < 4; q4++) acc[nt][q4] = 0.f;
        if (warp < 13) {
            const int m0 = warp << 4;
#pragma unroll
            for (int ks = 0; ks < 4; ks++) {
                uint32_t A[4], B[8][2];
                ldsm4(sb + A_QF + (m0 + aRow) * 144 + (ks * 16 + aK) * 2, A);
#pragma unroll
                for (int n2 = 0; n2 < 4; n2++) {
                    uint32_t dr[4];
                    ldsm4(sb + A_CNT + (n2 * 16 + bRow) * 144 + (ks * 16 + bK2) * 2, dr);
                    B[n2 * 2][0] = dr[0]; B[n2 * 2][1] = dr[1];
                    B[n2 * 2 + 1][0] = dr[2]; B[n2 * 2 + 1][1] = dr[3];
                }
#pragma unroll
                for (int nt = 0; nt < 8; nt++) mma_f16(acc[nt], A, B[nt]);
            }
        }
        __syncthreads();          // qf/cnt dead -> o1b may overwrite
        if (warp < 13) {
            const int cg = lane >> 2, ctg = lane & 3;
            const int r0 = (warp << 4) + cg, r1 = r0 + 8;
#pragma unroll
            for (int nt = 0; nt < 8; nt++) {
                int col = nt * 8 + ctg * 2;
                if (r0 < 196) {
                    o1b[r0 * 64 + col]     = acc[nt][0];
                    o1b[r0 * 64 + col + 1] = acc[nt][1];
                }
                if (r1 < 196) {
                    o1b[r1 * 64 + col]     = acc[nt][2];
                    o1b[r1 * 64 + col + 1] = acc[nt][3];
                }
            }
        }
        __syncthreads();
        // attn_lif (th=0.5): state in regs, spikes -> g_s2h fp16
#pragma unroll 1
        for (int j = 0; j < 25; j++) {
            int n = g + 8 * j;
            if (n < 196) {
                float o1 = o1b[n * 64 + d] * 0.125f;
                float vv = vst[j];
                vv += (o1 - vv) * 0.5f;
                bool s = (vv >= 0.5f);
                vst[j] = s ? 0.f : vv;
                g_s2h[((size_t)((t * 64 + b) * 196 + n)) * 512 + h * 64 + d] =
                    __float2half(s ? 1.f : 0.f);
            }
        }
    }
}

// ---------------------------------------------------------------------------
extern "C" void kernel_launch(void* const* d_in, const int* in_sizes, int n_in,
                              void* d_out, int out_size) {
    const float* x     = (const float*)d_in[0];
    const float* w     = (const float*)d_in[2];
    const float* gamma = (const float*)d_in[3];
    const float* beta  = (const float*)d_in[4];
    const float* mean  = (const float*)d_in[5];
    const float* var   = (const float*)d_in[6];

    float* o_out    = (float*)d_out;
    float* attn_out = o_out + O_ELEMS;

    cudaFuncSetAttribute(mma_gemm_lif<0>, cudaFuncAttributeMaxDynamicSharedMemorySize, SMEMSZ);
    cudaFuncSetAttribute(mma_gemm_lif<1>, cudaFuncAttributeMaxDynamicSharedMemorySize, SMEMSZ);
    cudaFuncSetAttribute(attn_kernel, cudaFuncAttributeMaxDynamicSharedMemorySize, A_SZ);

    prep_all<<<32825, 256>>>(x, w, gamma, beta, mean, var);     // 1
    mma_gemm_lif<0><<<dim3(7, 12, 64), 256, SMEMSZ>>>(nullptr); // 2
    fixup_qkv<<<NBKT + 64, 128>>>(w);                           // 3
    attn_kernel<<<512, 512, A_SZ>>>(attn_out);                  // 4 <- ncu captures this
    mma_gemm_lif<1><<<dim3(7, 4, 64), 256, SMEMSZ>>>(o_out);    // 5
    fixup_proj<<<64, 256>>>(w, o_out);                          // 6
}

// round 15
// speedup vs baseline: 1.1438x; 1.1438x over previous
#include <cuda_runtime.h>
#include <cuda_fp16.h>
#include <cstdint>

// T=4, B=64, C=512, N=196, H=8, D=64
#define EPS_         1e-5f
#define MARGIN_QKV   2e-3f
#define MARGIN_PROJ  1.2e-3f

constexpr size_t BITS_SZ = 3ULL * 4 * 64 * 8 * 196;     // packed u64
constexpr size_t BR_BITS = 4ULL * 64 * 8 * 196;
constexpr size_t O_ELEMS = 4ULL * 64 * 512 * 196;
constexpr size_t XT_SZ   = 4ULL * 64 * 196 * 512;       // [t,b,n,c]
constexpr int CAP0 = 1 << 20;
constexpr int CAP1 = 1 << 18;
constexpr int STG    = 16384;            // stage: Wh@0 | Xh@8192, 64B pitch rows
constexpr int NSTAGE = 6;
constexpr int SMEMSZ = NSTAGE * STG;     // 98304 -> 2 CTAs/SM

// attn kernel smem layout (bytes)
constexpr int A_SQ  = 0;                 // u64[200]
constexpr int A_SK  = 1600;
constexpr int A_SV  = 3200;
constexpr int A_KC  = 4800;              // u64[64][4]
constexpr int A_VC  = 6848;
constexpr int A_VST = 8960;              // f32[196*64] LIF state
constexpr int A_QF  = 59136;             // fp16 [208][pitch 144B]
constexpr int A_CNT = 89088;             // fp16 [64][pitch 144B]
constexpr int A_O1  = 59136;             // f32 [196*64] (aliases QF/CNT after mma)
constexpr int A_SZ  = 109312;

__device__ __align__(16) unsigned long long g_bits[BITS_SZ];
__device__ __align__(16) float              g_xT[XT_SZ];     // fp32 (fixup only)
__device__ __align__(16) __half             g_xh[XT_SZ];
__device__ __align__(16) __half             g_s2h[XT_SZ];    // attn_lif spikes fp16
__device__ __align__(16) __half             g_wh[2048 * 512];
__device__ float    g_inv[2048];
__device__ float    g_shift[2048];
__device__ unsigned g_fix0[CAP0];
__device__ unsigned g_fix1[CAP1];
__device__ int      g_cnt[2];

// ---------------------------------------------------------------------------
// Fused prep: [0,4096) w->fp16 | [4096,32768) x_split | [32768,32776) bn+cnt
// ---------------------------------------------------------------------------
__global__ void prep_all(const float* __restrict__ x,     const float* __restrict__ w,
                         const float* __restrict__ gamma, const float* __restrict__ beta,
                         const float* __restrict__ mean,  const float* __restrict__ var) {
    __shared__ float tile[32][33];
    const int bid = blockIdx.x, tid = threadIdx.x;
    if (bid < 4096) {                       // w fp32 -> fp16
        int i = bid * 256 + tid;
        g_wh[i] = __float2half(w[i]);
    } else if (bid < 32768) {               // x [t,b,c,n] -> xT f32 + xh fp16 [t,b,n,c]
        int id = bid - 4096;
        int c0 = (id & 15) * 32, n0 = ((id >> 4) % 7) * 32, tb = id / 112;
        int tx = tid & 31, ty = tid >> 5;
#pragma unroll
        for (int i = 0; i < 4; i++) {
            int c = ty + i * 8, n = tx;
            float v = (n0 + n < 196) ? x[((size_t)tb * 512 + c0 + c) * 196 + n0 + n] : 0.f;
            tile[c][n] = v;
        }
        __syncthreads();
#pragma unroll
        for (int i = 0; i < 4; i++) {
            int n = ty + i * 8, c = tx;
            if (n0 + n < 196) {
                size_t idx = ((size_t)tb * 196 + n0 + n) * 512 + c0 + c;
                float v = tile[c][n];
                g_xT[idx] = v;
                g_xh[idx] = __float2half(v);
            }
        }
    } else {                                // BN prep + counter zero
        int i = (bid - 32768) * 256 + tid;
        if (bid == 32768 && tid < 2) g_cnt[tid] = 0;
        if (i < 2048) {
            float inv = gamma[i] * rsqrtf(var[i] + EPS_);
            g_inv[i]   = inv;
            g_shift[i] = beta[i] - mean[i] * inv;
        }
    }
}

// ---------------------------------------------------------------------------
__device__ __forceinline__ void ldsm4(uint32_t addr, uint32_t* d) {
    asm volatile("ldmatrix.sync.aligned.m8n8.x4.shared.b16 {%0,%1,%2,%3}, [%4];"
        : "=r"(d[0]), "=r"(d[1]), "=r"(d[2]), "=r"(d[3]) : "r"(addr));
}
__device__ __forceinline__ void mma_f16(float* c, const uint32_t* a, const uint32_t* b) {
    asm volatile(
        "mma.sync.aligned.m16n8k16.row.col.f32.f16.f16.f32 "
        "{%0,%1,%2,%3}, {%4,%5,%6,%7}, {%8,%9}, {%0,%1,%2,%3};"
        : "+f"(c[0]), "+f"(c[1]), "+f"(c[2]), "+f"(c[3])
        : "r"(a[0]), "r"(a[1]), "r"(a[2]), "r"(a[3]), "r"(b[0]), "r"(b[1]));
}
__device__ __forceinline__ void cpa16(uint32_t dst, const void* src) {
    asm volatile("cp.async.cg.shared.global [%0], [%1], 16;" :: "r"(dst), "l"(src));
}
// XOR-swizzled address: 64B rows, chunk q permuted by ((row>>1)&3).
__device__ __forceinline__ uint32_t sw_addr(uint32_t base, int row, int kElem) {
    int q = kElem >> 3;
    return base + row * 64 + (((q ^ ((row >> 1) & 3)) << 4));
}

// One stage load (256 thr): regions Wh@0, Xh@8192 (128 rows x 64B each).
template<int IS_PROJ>
__device__ __forceinline__ void stage_load(uint32_t sbase, int kc, int wrow0, int b, int n0) {
    const __half* __restrict__ xs = IS_PROJ ? g_s2h : g_xh;
#pragma unroll
    for (int p = 0; p < 2; p++) {
        int c = threadIdx.x * 2 + p;
        int row = c >> 2, q = c & 3;
        uint32_t doff = (uint32_t)(row * 64 + ((q ^ ((row >> 1) & 3)) << 4));
        cpa16(sbase + doff, g_wh + (size_t)(wrow0 + row) * 512 + kc + q * 8);
        int t = row >> 5, n = row & 31;
        cpa16(sbase + 8192 + doff,
              xs + ((size_t)((t * 64 + b) * 196 + n0 + n)) * 512 + kc + q * 8);
    }
    asm volatile("cp.async.commit_group;");
}

// ---------------------------------------------------------------------------
// SINGLE-PASS fp16 mma.sync GEMM + BN + LIF. 6-stage cp.async, 2 CTAs/SM.
// ---------------------------------------------------------------------------
template<int IS_PROJ>
__global__ __launch_bounds__(256, 2) void mma_gemm_lif(float* __restrict__ o_out) {
    extern __shared__ __align__(16) unsigned char SM[];
    const int n0   = min((int)blockIdx.x * 32, 164);   // overlap tile: all n valid
    const int o128 = blockIdx.y << 7;
    const int b    = blockIdx.z;
    const int wrow0 = (IS_PROJ ? 1536 : 0) + o128;
    const int tid = threadIdx.x, lane = tid & 31, warp = tid >> 5;
    const int wt = warp & 3, oh = warp >> 2;
    const float MARGIN = IS_PROJ ? MARGIN_PROJ : MARGIN_QKV;
    const uint32_t sb = (uint32_t)__cvta_generic_to_shared(SM);

    float acc[4][4][4];
#pragma unroll
    for (int a = 0; a < 4; a++)
#pragma unroll
        for (int c = 0; c < 4; c++)
#pragma unroll
            for (int d = 0; d < 4; d++) acc[a][c][d] = 0.f;

    const int aRow = lane & 15,                aK = (lane >> 4) << 3;
    const int bRow = (lane & 7) | ((lane >> 4) << 3), bK = ((lane >> 3) & 1) << 3;

#pragma unroll
    for (int s = 0; s < 5; s++)
        stage_load<IS_PROJ>(sb + s * STG, s * 32, wrow0, b, n0);

#pragma unroll 1
    for (int i = 0; i < 16; i++) {
        if (i <= 11)      asm volatile("cp.async.wait_group 4;");
        else if (i == 12) asm volatile("cp.async.wait_group 3;");
        else if (i == 13) asm volatile("cp.async.wait_group 2;");
        else if (i == 14) asm volatile("cp.async.wait_group 1;");
        else              asm volatile("cp.async.wait_group 0;");
        __syncthreads();
        if (i + 5 < 16)
            stage_load<IS_PROJ>(sb + ((i + 5) % 6) * STG, (i + 5) * 32, wrow0, b, n0);

        const uint32_t st  = sb + (i % 6) * STG;
        const uint32_t s_x = st + 8192;
#pragma unroll
        for (int kk = 0; kk < 32; kk += 16) {
            uint32_t A[4][4], B[4][2];
#pragma unroll
            for (int ot = 0; ot < 4; ot++)
                ldsm4(sw_addr(st, oh * 64 + ot * 16 + aRow, kk + aK), A[ot]);
#pragma unroll
            for (int n2 = 0; n2 < 2; n2++) {
                uint32_t d[4];
                ldsm4(sw_addr(s_x, wt * 32 + n2 * 16 + bRow, kk + bK), d);
                B[n2 * 2][0] = d[0]; B[n2 * 2][1] = d[1];
                B[n2 * 2 + 1][0] = d[2]; B[n2 * 2 + 1][1] = d[3];
            }
#pragma unroll
            for (int ot = 0; ot < 4; ot++)
#pragma unroll
                for (int nt = 0; nt < 4; nt++) mma_f16(acc[ot][nt], A[ot], B[nt]);
        }
    }

    // ---- epilogue: acc -> ys[4t][128o][33] (smem), then BN + LIF
    __syncthreads();
    float* ys = (float*)SM;
    {
        const int cg = lane >> 2, ctg = lane & 3;
#pragma unroll
        for (int ot = 0; ot < 4; ot++)
#pragma unroll
            for (int nt = 0; nt < 4; nt++) {
                int row = oh * 64 + ot * 16 + cg, col = nt * 8 + ctg * 2;
                ys[(wt * 128 + row) * 33 + col]         = acc[ot][nt][0];
                ys[(wt * 128 + row) * 33 + col + 1]     = acc[ot][nt][1];
                ys[(wt * 128 + row + 8) * 33 + col]     = acc[ot][nt][2];
                ys[(wt * 128 + row + 8) * 33 + col + 1] = acc[ot][nt][3];
            }
    }
    __syncthreads();

    if (!IS_PROJ) {
        const int oq2 = warp & 3, ng = warp >> 2;
        const int o_loc = oq2 * 32 + lane;
        const int og = o128 + o_loc;
        const int br = og >> 9, o_in = og & 511;
        const float inv = g_inv[br * 512 + o_in], shf = g_shift[br * 512 + o_in];
        const int h = (o_in >> 6) & 7, half = (o_loc >> 5) & 1;
#pragma unroll
        for (int j = 0; j < 16; j++) {
            const int nl = ng * 16 + j, n = n0 + nl;
            float v = 0.f;
            bool bad = false, sp[4];
#pragma unroll
            for (int t = 0; t < 4; t++) {
                float y = fmaf(ys[(t * 128 + o_loc) * 33 + nl], inv, shf);
                v += (y - v) * 0.5f;
                float d = v - 1.0f;
                if (fabsf(d) < MARGIN) bad = true;
                sp[t] = d >= 0.f;
                if (sp[t]) v = 0.f;
            }
#pragma unroll
            for (int t = 0; t < 4; t++) {
                uint32_t m = __ballot_sync(0xffffffffu, sp[t]);
                if (lane == 0)
                    ((uint32_t*)g_bits)[((((size_t)br * 4 + t) * 64 + b) * 8 + h) * 392
                                        + n * 2 + half] = m;
            }
            if (bad) {
                int s = atomicAdd(&g_cnt[0], 1);
                if (s < CAP0)
                    g_fix0[s] = ((unsigned)br << 23) | ((unsigned)b << 17) |
                                ((unsigned)o_in << 8) | n;
            }
        }
    } else {
        const int n = n0 + lane;
#pragma unroll
        for (int j = 0; j < 16; j++) {
            const int o_in = o128 + warp * 16 + j;
            const float inv = g_inv[1536 + o_in], shf = g_shift[1536 + o_in];
            float v = 0.f;
            bool bad = false;
#pragma unroll
            for (int t = 0; t < 4; t++) {
                float y = fmaf(ys[(t * 128 + warp * 16 + j) * 33 + lane], inv, shf);
                v += (y - v) * 0.5f;
                float d = v - 1.0f;
                if (fabsf(d) < MARGIN) bad = true;
                bool s = d >= 0.f;
                o_out[((size_t)(t * 64 + b) * 512 + o_in) * 196 + n] = s ? 1.f : 0.f;
                if (s) v = 0.f;
            }
            if (bad) {
                int s = atomicAdd(&g_cnt[1], 1);
                if (s < CAP1)
                    g_fix1[s] = ((unsigned)b << 17) | ((unsigned)o_in << 8) | n;
            }
        }
    }
}

// ---------------------------------------------------------------------------
// Fixup: exact fp32 recompute, STRICT sequential c order WITHIN each t-chain
// (bit-identical to before), but the 4 independent t-dots run as interleaved
// accumulators -> 4-way ILP on the latency-bound FMA chains.
// ---------------------------------------------------------------------------
template<int IS_PROJ>
__global__ void fixup(const float* __restrict__ w, float* __restrict__ o_out) {
    int cnt = g_cnt[IS_PROJ];
    int cap = IS_PROJ ? CAP1 : CAP0;
    if (cnt > cap) cnt = cap;
    for (int e = blockIdx.x * blockDim.x + threadIdx.x; e < cnt;
         e += gridDim.x * blockDim.x) {
        unsigned u = IS_PROJ ? g_fix1[e] : g_fix0[e];
        int n = u & 255, o = (u >> 8) & 511, bb = (u >> 17) & 63;
        int br = IS_PROJ ? 3 : (int)(u >> 23);
        const float* wr = w + ((size_t)br * 512 + o) * 512;
        float inv = g_inv[br * 512 + o], shf = g_shift[br * 512 + o];
        float s0 = 0.f, s1 = 0.f, s2 = 0.f, s3 = 0.f;
        if (IS_PROJ) {
            const __half* x0 = g_s2h + ((size_t)((0 * 64 + bb) * 196 + n)) * 512;
            const __half* x1 = g_s2h + ((size_t)((1 * 64 + bb) * 196 + n)) * 512;
            const __half* x2 = g_s2h + ((size_t)((2 * 64 + bb) * 196 + n)) * 512;
            const __half* x3 = g_s2h + ((size_t)((3 * 64 + bb) * 196 + n)) * 512;
#pragma unroll 4
            for (int c = 0; c < 512; c += 2) {
                float wa = wr[c], wbv = wr[c + 1];
                __half2 p0 = *(const __half2*)(x0 + c);
                __half2 p1 = *(const __half2*)(x1 + c);
                __half2 p2 = *(const __half2*)(x2 + c);
                __half2 p3 = *(const __half2*)(x3 + c);
                s0 = fmaf(wa, __low2float(p0), s0); s0 = fmaf(wbv, __high2float(p0), s0);
                s1 = fmaf(wa, __low2float(p1), s1); s1 = fmaf(wbv, __high2float(p1), s1);
                s2 = fmaf(wa, __low2float(p2), s2); s2 = fmaf(wbv, __high2float(p2), s2);
                s3 = fmaf(wa, __low2float(p3), s3); s3 = fmaf(wbv, __high2float(p3), s3);
            }
        } else {
            const float* x0 = g_xT + ((size_t)((0 * 64 + bb) * 196 + n)) * 512;
            const float* x1 = g_xT + ((size_t)((1 * 64 + bb) * 196 + n)) * 512;
            const float* x2 = g_xT + ((size_t)((2 * 64 + bb) * 196 + n)) * 512;
            const float* x3 = g_xT + ((size_t)((3 * 64 + bb) * 196 + n)) * 512;
#pragma unroll 2
            for (int c = 0; c < 512; c += 4) {
                float4 a  = *(const float4*)(wr + c);
                float4 v0 = *(const float4*)(x0 + c);
                float4 v1 = *(const float4*)(x1 + c);
                float4 v2 = *(const float4*)(x2 + c);
                float4 v3 = *(const float4*)(x3 + c);
                s0 = fmaf(a.x, v0.x, s0); s0 = fmaf(a.y, v0.y, s0);
                s0 = fmaf(a.z, v0.z, s0); s0 = fmaf(a.w, v0.w, s0);
                s1 = fmaf(a.x, v1.x, s1); s1 = fmaf(a.y, v1.y, s1);
                s1 = fmaf(a.z, v1.z, s1); s1 = fmaf(a.w, v1.w, s1);
                s2 = fmaf(a.x, v2.x, s2); s2 = fmaf(a.y, v2.y, s2);
                s2 = fmaf(a.z, v2.z, s2); s2 = fmaf(a.w, v2.w, s2);
                s3 = fmaf(a.x, v3.x, s3); s3 = fmaf(a.y, v3.y, s3);
                s3 = fmaf(a.z, v3.z, s3); s3 = fmaf(a.w, v3.w, s3);
            }
        }
        float yv[4] = {s0, s1, s2, s3};
        float v = 0.f;
#pragma unroll
        for (int t = 0; t < 4; t++) {
            float y = fmaf(yv[t], inv, shf);
            v += (y - v) * 0.5f;
            bool sp = (v - 1.0f) >= 0.f;
            if (IS_PROJ) {
                o_out[((size_t)(t * 64 + bb) * 512 + o) * 196 + n] = sp ? 1.f : 0.f;
            } else {
                int h = o >> 6, d = o & 63;
                uint32_t* wp = ((uint32_t*)g_bits) +
                    ((((size_t)br * 4 + t) * 64 + bb) * 8 + h) * 392 + n * 2 + (d >> 5);
                uint32_t m = 1u << (d & 31);
                if (sp) atomicOr(wp, m); else atomicAnd(wp, ~m);
            }
            if (sp) v = 0.f;
        }
    }
}

// ---------------------------------------------------------------------------
// Attention per (b,h), all 4 t in-block (R13 version: 195us measured).
//   attn[n,m] = popc(q&k)/8 (streamed, warp-per-row).
//   o1 = qf @ cnt_d via m16n8k16 fp16 MMA (all-integer => EXACT).
//   LIF state (vstate) in smem; o1_buf aliases qf/cnt after the mma.
// ---------------------------------------------------------------------------
__global__ __launch_bounds__(512) void attn_kernel(float* __restrict__ attn_out) {
    extern __shared__ __align__(16) unsigned char AS[];
    const int bh = blockIdx.x;
    const int b = bh >> 3, h = bh & 7;

    unsigned long long* sq = (unsigned long long*)(AS + A_SQ);
    unsigned long long* sk = (unsigned long long*)(AS + A_SK);
    unsigned long long* sv = (unsigned long long*)(AS + A_SV);
    unsigned long long* kc = (unsigned long long*)(AS + A_KC);   // [e*4+w]
    unsigned long long* vc = (unsigned long long*)(AS + A_VC);
    float* vstate = (float*)(AS + A_VST);
    float* o1b    = (float*)(AS + A_O1);
    const uint32_t sb = (uint32_t)__cvta_generic_to_shared(AS);

    const int tid = threadIdx.x;
    const int d = tid & 63, g = tid >> 6;
    const int warp = tid >> 5, lane = tid & 31;
    const int aRow = lane & 15, aK = (lane >> 4) << 3;
    const int bRow = (lane & 7) | ((lane >> 4) << 3), bK2 = ((lane >> 3) & 1) << 3;

    for (int i = tid; i < 12544; i += 512) vstate[i] = 0.f;

#pragma unroll 1
    for (int t = 0; t < 4; t++) {
        __syncthreads();
        size_t qidx = ((size_t)(t * 64 + b) * 8 + h) * 196;
        for (int i = tid; i < 600; i += 512) {
            if (i < 196)      sq[i]       = g_bits[qidx + i];
            else if (i < 392) sk[i - 196] = g_bits[BR_BITS + qidx + (i - 196)];
            else if (i < 588) sv[i - 392] = g_bits[2 * BR_BITS + qidx + (i - 392)];
            else {
                int j = i - 588;
                if (j < 4)      sq[196 + j] = 0ull;
                else if (j < 8) sk[192 + j] = 0ull;
                else            sv[188 + j] = 0ull;
            }
        }
        __syncthreads();
        // kcol/vcol (512-thread map) + qf build (fp16 0/1 from bits)
        {
            int e = tid & 63, wd = (tid >> 6) & 3, sel = tid >> 8;
            const unsigned long long* src = sel ? sv : sk;
            int m0 = wd * 64;
            int m1 = m0 + 64 < 196 ? m0 + 64 : 196;
            unsigned long long a = 0ull;
            for (int m = m0; m < m1; m++)
                a |= ((src[m] >> e) & 1ull) << (m - m0);
            if (sel) vc[e * 4 + wd] = a; else kc[e * 4 + wd] = a;
        }
        for (int i = tid; i < 208 * 32; i += 512) {
            int n = i >> 5, ep = (i & 31) << 1;
            unsigned long long bits = (n < 196) ? sq[n] : 0ull;
            __half2 hv = __floats2half2_rn((float)((bits >> ep) & 1ull),
                                           (float)((bits >> (ep + 1)) & 1ull));
            *(__half2*)(AS + A_QF + n * 144 + ep * 2) = hv;
        }
        __syncthreads();
        // attn output (warp-per-row, coalesced over m) + cnt_d build (fp16)
        {
            size_t abase = ((size_t)(t * 64 + b) * 8 + h) * 38416;
#pragma unroll 1
            for (int r = 0; r < 13; r++) {
                int n = warp + (r << 4);
                if (n < 196) {
                    unsigned long long qn = sq[n];
                    float* out = attn_out + abase + n * 196;
                    for (int m = lane; m < 196; m += 32)
                        out[m] = (float)__popcll(qn & sk[m]) * 0.125f;
                }
            }
        }
        for (int i = tid; i < 4096; i += 512) {
            int dd = i >> 6, e = i & 63;
            int c = __popcll(kc[e * 4] & vc[dd * 4]) + __popcll(kc[e * 4 + 1] & vc[dd * 4 + 1])
                  + __popcll(kc[e * 4 + 2] & vc[dd * 4 + 2]) + __popcll(kc[e * 4 + 3] & vc[dd * 4 + 3]);
            *(__half*)(AS + A_CNT + dd * 144 + e * 2) = __int2half_rn(c);   // c<=196 exact
        }
        __syncthreads();
        // o1 = qf @ cnt_d  (13 m-tiles x 8 d-tiles, exact integer math)
        float acc[8][4];
#pragma unroll
        for (int nt = 0; nt < 8; nt++)
#pragma unroll
            for (int q4 = 0; q4 < 4; q4++) acc[nt][q4] = 0.f;
        if (warp < 13) {
            const int m0 = warp << 4;
#pragma unroll
            for (int ks = 0; ks < 4; ks++) {
                uint32_t A[4], B[8][2];
                ldsm4(sb + A_QF + (m0 + aRow) * 144 + (ks * 16 + aK) * 2, A);
#pragma unroll
                for (int n2 = 0; n2 < 4; n2++) {
                    uint32_t dr[4];
                    ldsm4(sb + A_CNT + (n2 * 16 + bRow) * 144 + (ks * 16 + bK2) * 2, dr);
                    B[n2 * 2][0] = dr[0]; B[n2 * 2][1] = dr[1];
                    B[n2 * 2 + 1][0] = dr[2]; B[n2 * 2 + 1][1] = dr[3];
                }
#pragma unroll
                for (int nt = 0; nt < 8; nt++) mma_f16(acc[nt], A, B[nt]);
            }
        }
        __syncthreads();          // all reads of qf/cnt done -> o1b may overwrite
        if (warp < 13) {
            const int cg = lane >> 2, ctg = lane & 3;
            const int r0 = (warp << 4) + cg, r1 = r0 + 8;
#pragma unroll
            for (int nt = 0; nt < 8; nt++) {
                int col = nt * 8 + ctg * 2;
                if (r0 < 196) {
                    o1b[r0 * 64 + col]     = acc[nt][0];
                    o1b[r0 * 64 + col + 1] = acc[nt][1];
                }
                if (r1 < 196) {
                    o1b[r1 * 64 + col]     = acc[nt][2];
                    o1b[r1 * 64 + col + 1] = acc[nt][3];
                }
            }
        }
        __syncthreads();
        // attn_lif (th=0.5): state in smem, spikes -> g_s2h fp16 (coalesced)
#pragma unroll 1
        for (int j = 0; j < 25; j++) {
            int n = g + 8 * j;
            if (n < 196) {
                float o1 = o1b[n * 64 + d] * 0.125f;
                float vv = vstate[n * 64 + d];
                vv += (o1 - vv) * 0.5f;
                bool s = (vv >= 0.5f);
                vstate[n * 64 + d] = s ? 0.f : vv;
                g_s2h[((size_t)((t * 64 + b) * 196 + n)) * 512 + h * 64 + d] =
                    __float2half(s ? 1.f : 0.f);
            }
        }
    }
}

// ---------------------------------------------------------------------------
extern "C" void kernel_launch(void* const* d_in, const int* in_sizes, int n_in,
                              void* d_out, int out_size) {
    const float* x     = (const float*)d_in[0];
    const float* w     = (const float*)d_in[2];
    const float* gamma = (const float*)d_in[3];
    const float* beta  = (const float*)d_in[4];
    const float* mean  = (const float*)d_in[5];
    const float* var   = (const float*)d_in[6];

    float* o_out    = (float*)d_out;
    float* attn_out = o_out + O_ELEMS;

    cudaFuncSetAttribute(mma_gemm_lif<0>, cudaFuncAttributeMaxDynamicSharedMemorySize, SMEMSZ);
    cudaFuncSetAttribute(mma_gemm_lif<1>, cudaFuncAttributeMaxDynamicSharedMemorySize, SMEMSZ);
    cudaFuncSetAttribute(attn_kernel, cudaFuncAttributeMaxDynamicSharedMemorySize, A_SZ);

    prep_all<<<32776, 256>>>(x, w, gamma, beta, mean, var);     // 1
    mma_gemm_lif<0><<<dim3(7, 12, 64), 256, SMEMSZ>>>(nullptr); // 2
    fixup<0><<<256, 256>>>(w, nullptr);                         // 3
    attn_kernel<<<512, 512, A_SZ>>>(attn_out);                  // 4 <- ncu captures this
    mma_gemm_lif<1><<<dim3(7, 4, 64), 256, SMEMSZ>>>(o_out);    // 5
    fixup<1><<<64, 256>>>(w, o_out);                            // 6
}